// round 11
// baseline (speedup 1.0000x reference)
#include <cuda_runtime.h>
#include <cuda_fp16.h>
#include <cstdint>

// ---------------------------------------------------------------------------
// HierarchUpdateMlp — fp16 mma.sync m16n8k16, fp32 accum. R9: K-chunk 64
// (was 32) to halve per-chunk overhead (barrier/wait/issue) per MMA; R6
// structure otherwise (8 warps, warp tile 64x64, stride-36 b32 smem rows).
//   k<0>: stage A, 7 GEMMs (CTA 256x128, K=1280/512) -> g_out1h (fp16)
//   k<1>: stage B, 6 GEMMs (CTA 256x128, K=256, pair gather) -> g_out2h
//   k<2>: stage C, GEMM  (CTA 128x256, K=768) -> out (fp32)
// ---------------------------------------------------------------------------

#define NPAD 50176  // = ceil(50000/256)*256

__device__ __align__(16) __half g_out1h[(size_t)NPAD * 896];
__device__ __align__(16) __half g_out2h[(size_t)NPAD * 768];
__device__ __align__(16) __half g_W10h[128 * 1280];
__device__ __align__(16) __half g_W1h[6 * 128 * 512];
__device__ __align__(16) __half g_W2h[6 * 128 * 256];
__device__ __align__(16) __half g_Wfh[256 * 768];

#define STG_U32 13824            // (AM+BN)*36 = 384*36 u32 per 64-K stage
#define STG_BYTES (STG_U32 * 4)  // 55296 B

__device__ __forceinline__ uint32_t smaddr(const void* p) {
    uint32_t a;
    asm("{ .reg .u64 t; cvta.to.shared.u64 t, %1; cvt.u32.u64 %0, t; }"
        : "=r"(a) : "l"(p));
    return a;
}
__device__ __forceinline__ uint32_t packh(float hi, float lo) {
    uint32_t r;
    asm("cvt.rn.f16x2.f32 %0, %1, %2;" : "=r"(r) : "f"(hi), "f"(lo));
    return r;
}
__device__ __forceinline__ void cpa_cg(uint32_t d, const void* s) {
    asm volatile("cp.async.cg.shared.global [%0], [%1], 16;" :: "r"(d), "l"(s)
                 : "memory");
}
__device__ __forceinline__ void cp_commit() {
    asm volatile("cp.async.commit_group;" ::: "memory");
}
__device__ __forceinline__ void cp_wait(int allowed) {
    if (allowed >= 2) asm volatile("cp.async.wait_group 2;" ::: "memory");
    else if (allowed == 1) asm volatile("cp.async.wait_group 1;" ::: "memory");
    else asm volatile("cp.async.wait_group 0;" ::: "memory");
}
__device__ __forceinline__ void sts64(uint32_t a, uint32_t x, uint32_t y) {
    asm volatile("st.shared.v2.b32 [%0], {%1,%2};" :: "r"(a), "r"(x), "r"(y)
                 : "memory");
}
__device__ __forceinline__ void mma16(float (&c)[4], const unsigned (&a)[4],
                                      const unsigned (&b)[2]) {
    asm volatile(
        "mma.sync.aligned.m16n8k16.row.col.f32.f16.f16.f32 "
        "{%0,%1,%2,%3},{%4,%5,%6,%7},{%8,%9},{%0,%1,%2,%3};\n"
        : "+f"(c[0]), "+f"(c[1]), "+f"(c[2]), "+f"(c[3])
        : "r"(a[0]), "r"(a[1]), "r"(a[2]), "r"(a[3]), "r"(b[0]), "r"(b[1]));
}

// ---------------------------------------------------------------------------
__global__ void cvt_weights(const float* __restrict__ W10,
                            const float* __restrict__ W1,
                            const float* __restrict__ W2,
                            const float* __restrict__ Wf) {
    int i = blockIdx.x * blockDim.x + threadIdx.x;
    int st = gridDim.x * blockDim.x;
    for (int j = i; j < 128 * 1280; j += st) g_W10h[j] = __float2half_rn(W10[j]);
    for (int j = i; j < 6 * 128 * 512; j += st) g_W1h[j] = __float2half_rn(W1[j]);
    for (int j = i; j < 6 * 128 * 256; j += st) g_W2h[j] = __float2half_rn(W2[j]);
    for (int j = i; j < 256 * 768; j += st) g_Wfh[j] = __float2half_rn(Wf[j]);
}

// ---------------------------------------------------------------------------
// MODE 0: A=update fp32 (LDG->cvt(pack)->STS, 2 stages), out fp16. CTA 256x128.
// MODE 1: A=g_out1h (cp.async, 4-stage ring), out fp16.            CTA 256x128.
// MODE 2: A=g_out2h (cp.async, 4-stage ring), out fp32.            CTA 128x256.
// 8 warps, warp tile 64x64: modes 0/1 -> 4m x 2n, mode 2 -> 2m x 4n.
// K-chunk 64: rows are 32 b32 (64 fp16) padded to stride 36 (conflict-free).
// ---------------------------------------------------------------------------
template <int MODE>
__global__ __launch_bounds__(256, 1)
void gemm_h(const float* __restrict__ Aupd, const float* __restrict__ bias0,
            const float* __restrict__ bias1, float* __restrict__ outp, int N) {
    extern __shared__ __align__(16) uint32_t smu[];

    constexpr int AM = (MODE == 2) ? 128 : 256;
    constexpr int BN = (MODE == 2) ? 256 : 128;

    const int tid = threadIdx.x;
    const int lane = tid & 31, warp = tid >> 5;
    const int wm = (MODE == 2) ? (warp >> 2) : (warp >> 1);
    const int wn = (MODE == 2) ? (warp & 3) : (warp & 1);
    const int qr = lane >> 2, qc = lane & 3;
    const int row0 = blockIdx.x * AM;
    const int g = blockIdx.y;
    const uint32_t smb = smaddr(smu);

    int K, ldB, j1 = 0, j2 = 0, c1 = 0, c2 = 0;
    const __half* Bsrc;
    const float* bias;
    const __half* Ah = nullptr;
    int ldA = 0, ldO = 0, colO = 0;
    __half* Dh = nullptr;
    if (MODE == 0) {
        if (g == 0) { K = 1280; Bsrc = g_W10h; ldB = 1280; bias = bias0; }
        else {
            const int p1[6] = {5, 7, 8, 11, 13, 14};
            const int p2[6] = {6, 9, 10, 12, 15, 16};
            K = 512; Bsrc = g_W1h + (size_t)(g - 1) * 65536; ldB = 512;
            bias = bias1 + (g - 1) * 128;
            j1 = p1[g - 1]; j2 = p2[g - 1];
        }
        Dh = g_out1h; ldO = 896; colO = g * 128;
    } else if (MODE == 1) {
        const int q1[6] = {0, 1, 1, 1, 4, 4};
        const int q2[6] = {1, 2, 3, 4, 5, 6};
        K = 256; Bsrc = g_W2h + (size_t)g * 32768; ldB = 256;
        bias = bias0 + g * 128;
        c1 = q1[g] * 128; c2 = q2[g] * 128;
        Ah = g_out1h; ldA = 896; Dh = g_out2h; ldO = 768; colO = g * 128;
    } else {
        K = 768; Bsrc = g_Wfh; ldB = 768; bias = bias0;
        Ah = g_out2h; ldA = 768;
    }
    const int nk = K >> 6;  // 64-K chunks

    float acc[4][8][4];
#pragma unroll
    for (int i = 0; i < 4; i++)
#pragma unroll
        for (int j = 0; j < 8; j++)
#pragma unroll
            for (int k = 0; k < 4; k++) acc[i][j][k] = 0.f;

    // ---- compute one 64-K chunk: 4 k16-steps x 32 MMAs ----
    auto compute = [&](int stage) {
        const uint32_t* Au = smu + stage * STG_U32;
        const uint32_t* Bu = Au + AM * 36;
#pragma unroll
        for (int s = 0; s < 4; s++) {
            const int o = 8 * s;
            unsigned a[4][4], b[8][2];
#pragma unroll
            for (int mt = 0; mt < 4; mt++) {
                const uint32_t* p = Au + (wm * 64 + mt * 16 + qr) * 36 + o + qc;
                a[mt][0] = p[0];
                a[mt][1] = p[288];   // +8 rows * 36
                a[mt][2] = p[4];
                a[mt][3] = p[292];
            }
#pragma unroll
            for (int nt = 0; nt < 8; nt++) {
                const uint32_t* p = Bu + (wn * 64 + nt * 8 + qr) * 36 + o + qc;
                b[nt][0] = p[0];
                b[nt][1] = p[4];
            }
#pragma unroll
            for (int mt = 0; mt < 4; mt++)
#pragma unroll
                for (int nt = 0; nt < 8; nt++) mma16(acc[mt][nt], a[mt], b[nt]);
        }
    };

    if (MODE == 0) {
        // ---- A: LDG fp32 -> pack fp16x2 regs -> STS; B: cp.async; 2 stages --
        uint32_t au[32];
        auto ldgA = [&](int ci) {
            const int k0 = ci * 64;
            const int joff =
                (g == 0) ? k0
                         : ((k0 < 256) ? (j1 * 256 + k0) : (j2 * 256 + k0 - 256));
#pragma unroll
            for (int u = 0; u < 16; u++) {
                const int idx = tid + u * 256, row = idx >> 4, seg = idx & 15;
                int r = row0 + row;
                if (r > N - 1) r = N - 1;
                const float4 v =
                    *(const float4*)(Aupd + (size_t)r * 4352 + joff + seg * 4);
                au[2 * u] = packh(v.y, v.x);
                au[2 * u + 1] = packh(v.w, v.z);
            }
        };
        auto stsA = [&](int stage) {
            const uint32_t base = smb + (uint32_t)stage * STG_BYTES;
#pragma unroll
            for (int u = 0; u < 16; u++) {
                const int idx = tid + u * 256, row = idx >> 4, seg = idx & 15;
                sts64(base + (uint32_t)(row * 36 + seg * 2) * 4, au[2 * u],
                      au[2 * u + 1]);
            }
        };
        auto cpB = [&](int ci, int stage) {
            const int k0 = ci * 64;
            const uint32_t Bb = smb + (uint32_t)stage * STG_BYTES + AM * 144;
#pragma unroll
            for (int u = 0; u < 4; u++) {  // 128 rows x 8 segs / 256 thr
                const int idx = tid + u * 256, row = idx >> 3, gs = idx & 7;
                cpa_cg(Bb + (uint32_t)(row * 36 + gs * 4) * 4,
                       Bsrc + (size_t)row * ldB + k0 + gs * 8);
            }
            cp_commit();
        };

        ldgA(0); stsA(0); cpB(0, 0);
        ldgA(1);
        for (int i = 0; i < nk; i++) {
            cp_wait(0);
            __syncthreads();
            if (i + 1 < nk) { stsA((i + 1) & 1); cpB(i + 1, (i + 1) & 1); }
            if (i + 2 < nk) ldgA(i + 2);
            compute(i & 1);
        }
    } else {
        // ---- A and B fp16 via cp.async; 4-stage ring, one barrier/chunk ----
        constexpr int AU = AM * 8 / 256;  // 16B loads per thread for A
        constexpr int BU = BN * 8 / 256;
        auto issue = [&](int ci) {
            const int k0 = ci * 64, stage = ci & 3;
            const uint32_t Abp = smb + (uint32_t)stage * STG_BYTES;
            const uint32_t Bbp = Abp + AM * 144;
            const int joff =
                (MODE == 1) ? ((k0 < 128) ? (c1 + k0) : (c2 + k0 - 128)) : k0;
#pragma unroll
            for (int u = 0; u < AU; u++) {
                const int idx = tid + u * 256, row = idx >> 3, gs = idx & 7;
                cpa_cg(Abp + (uint32_t)(row * 36 + gs * 4) * 4,
                       Ah + (size_t)(row0 + row) * ldA + joff + gs * 8);
            }
#pragma unroll
            for (int u = 0; u < BU; u++) {
                const int idx = tid + u * 256, row = idx >> 3, gs = idx & 7;
                cpa_cg(Bbp + (uint32_t)(row * 36 + gs * 4) * 4,
                       Bsrc + (size_t)row * ldB + k0 + gs * 8);
            }
            cp_commit();
        };

        issue(0); issue(1); issue(2);
        for (int i = 0; i < nk; i++) {
            const int rem = nk - 1 - i;
            cp_wait(rem < 2 ? rem : 2);
            __syncthreads();
            if (i + 3 < nk) issue(i + 3);
            compute(i & 3);
        }
    }

    // ---- epilogue: bias + relu ----
#pragma unroll
    for (int mt = 0; mt < 4; mt++) {
        const int r0 = row0 + wm * 64 + mt * 16 + qr;
#pragma unroll
        for (int nt = 0; nt < 8; nt++) {
            const int lc = wn * 64 + nt * 8 + 2 * qc;
            const float bb0 = __ldg(bias + lc);
            const float bb1 = __ldg(bias + lc + 1);
            const float v0 = fmaxf(acc[mt][nt][0] + bb0, 0.f);
            const float v1 = fmaxf(acc[mt][nt][1] + bb1, 0.f);
            const float v2 = fmaxf(acc[mt][nt][2] + bb0, 0.f);
            const float v3 = fmaxf(acc[mt][nt][3] + bb1, 0.f);
            if (MODE < 2) {
                if (r0 < N)
                    *(uint32_t*)&Dh[(size_t)r0 * ldO + colO + lc] = packh(v1, v0);
                if (r0 + 8 < N)
                    *(uint32_t*)&Dh[(size_t)(r0 + 8) * ldO + colO + lc] =
                        packh(v3, v2);
            } else {
                if (r0 < N)
                    *(float2*)&outp[(size_t)r0 * 256 + lc] = make_float2(v0, v1);
                if (r0 + 8 < N)
                    *(float2*)&outp[(size_t)(r0 + 8) * 256 + lc] =
                        make_float2(v2, v3);
            }
        }
    }
}

// ---------------------------------------------------------------------------
extern "C" void kernel_launch(void* const* d_in, const int* in_sizes, int n_in,
                              void* d_out, int out_size) {
    const float* upd = (const float*)d_in[0];
    const float* W10 = (const float*)d_in[1];
    const float* b10 = (const float*)d_in[2];
    const float* W1  = (const float*)d_in[3];
    const float* b1  = (const float*)d_in[4];
    const float* W2  = (const float*)d_in[5];
    const float* b2  = (const float*)d_in[6];
    const float* Wf  = (const float*)d_in[7];
    const float* bf  = (const float*)d_in[8];
    const int N = in_sizes[0] / (17 * 256);

    const int smem0 = 2 * STG_BYTES;   // 110592
    const int smem12 = 4 * STG_BYTES;  // 221184
    cudaFuncSetAttribute(gemm_h<0>, cudaFuncAttributeMaxDynamicSharedMemorySize, smem0);
    cudaFuncSetAttribute(gemm_h<1>, cudaFuncAttributeMaxDynamicSharedMemorySize, smem12);
    cudaFuncSetAttribute(gemm_h<2>, cudaFuncAttributeMaxDynamicSharedMemorySize, smem12);

    cvt_weights<<<256, 256>>>(W10, W1, W2, Wf);

    const int t256 = (N + 255) / 256;
    const int t128 = (N + 127) / 128;
    gemm_h<0><<<dim3(t256, 7), 256, smem0>>>(upd, b10, b1, nullptr, N);
    gemm_h<1><<<dim3(t256, 6), 256, smem12>>>(nullptr, b2, nullptr, nullptr, N);
    gemm_h<2><<<dim3(t128, 1), 256, smem12>>>(nullptr, bf, nullptr, (float*)d_out, N);
}

// round 12
// speedup vs baseline: 1.3211x; 1.3211x over previous
#include <cuda_runtime.h>
#include <cuda_fp16.h>
#include <cstdint>

// ---------------------------------------------------------------------------
// HierarchUpdateMlp — fp16 mma.sync m16n8k16, fp32 accum.
// R11: CTA 128x128, warp tile 64x32, __launch_bounds__(256,2) -> 2 CTAs/SM
// with INDEPENDENT barrier domains, so one CTA's MMA burst covers the other
// CTA's barrier/fragment-ramp bubble (the 63% tensor-idle seen in R6-R9).
//   k<0>: stage A, 7 GEMMs (K=1280/512) -> g_out1h (fp16)
//   k<1>: stage B, 6 GEMMs (K=256, pair gather) -> g_out2h (fp16)
//   k<2>: stage C, GEMM (K=768, 2 column-half CTAs) -> out (fp32)
// K-chunk 32, stride-20-b32 conflict-free smem rows (R6 layout).
// ---------------------------------------------------------------------------

#define NPAD 50176  // = ceil(50000/128)*128

__device__ __align__(16) __half g_out1h[(size_t)NPAD * 896];
__device__ __align__(16) __half g_out2h[(size_t)NPAD * 768];
__device__ __align__(16) __half g_W10h[128 * 1280];
__device__ __align__(16) __half g_W1h[6 * 128 * 512];
__device__ __align__(16) __half g_W2h[6 * 128 * 256];
__device__ __align__(16) __half g_Wfh[256 * 768];

#define STG_U32 5120             // (128+128)*20 u32 per stage
#define STG_BYTES (STG_U32 * 4)  // 20480 B

__device__ __forceinline__ uint32_t smaddr(const void* p) {
    uint32_t a;
    asm("{ .reg .u64 t; cvta.to.shared.u64 t, %1; cvt.u32.u64 %0, t; }"
        : "=r"(a) : "l"(p));
    return a;
}
__device__ __forceinline__ uint32_t packh(float hi, float lo) {
    uint32_t r;
    asm("cvt.rn.f16x2.f32 %0, %1, %2;" : "=r"(r) : "f"(hi), "f"(lo));
    return r;
}
__device__ __forceinline__ void cpa_cg(uint32_t d, const void* s) {
    asm volatile("cp.async.cg.shared.global [%0], [%1], 16;" :: "r"(d), "l"(s)
                 : "memory");
}
__device__ __forceinline__ void cp_commit() {
    asm volatile("cp.async.commit_group;" ::: "memory");
}
__device__ __forceinline__ void cp_wait(int allowed) {
    if (allowed >= 2) asm volatile("cp.async.wait_group 2;" ::: "memory");
    else if (allowed == 1) asm volatile("cp.async.wait_group 1;" ::: "memory");
    else asm volatile("cp.async.wait_group 0;" ::: "memory");
}
__device__ __forceinline__ void sts64(uint32_t a, uint32_t x, uint32_t y) {
    asm volatile("st.shared.v2.b32 [%0], {%1,%2};" :: "r"(a), "r"(x), "r"(y)
                 : "memory");
}
__device__ __forceinline__ void mma16(float (&c)[4], const unsigned (&a)[4],
                                      const unsigned (&b)[2]) {
    asm volatile(
        "mma.sync.aligned.m16n8k16.row.col.f32.f16.f16.f32 "
        "{%0,%1,%2,%3},{%4,%5,%6,%7},{%8,%9},{%0,%1,%2,%3};\n"
        : "+f"(c[0]), "+f"(c[1]), "+f"(c[2]), "+f"(c[3])
        : "r"(a[0]), "r"(a[1]), "r"(a[2]), "r"(a[3]), "r"(b[0]), "r"(b[1]));
}

// ---------------------------------------------------------------------------
__global__ void cvt_weights(const float* __restrict__ W10,
                            const float* __restrict__ W1,
                            const float* __restrict__ W2,
                            const float* __restrict__ Wf) {
    int i = blockIdx.x * blockDim.x + threadIdx.x;
    int st = gridDim.x * blockDim.x;
    for (int j = i; j < 128 * 1280; j += st) g_W10h[j] = __float2half_rn(W10[j]);
    for (int j = i; j < 6 * 128 * 512; j += st) g_W1h[j] = __float2half_rn(W1[j]);
    for (int j = i; j < 6 * 128 * 256; j += st) g_W2h[j] = __float2half_rn(W2[j]);
    for (int j = i; j < 256 * 768; j += st) g_Wfh[j] = __float2half_rn(Wf[j]);
}

// ---------------------------------------------------------------------------
// CTA 128x128 everywhere, 8 warps = 2m x 4n, warp tile 64x32, acc[4][4][4].
// MODE 0: A=update fp32 (LDG->pack->STS, 2 stages), B weights, out fp16.
// MODE 1: A=g_out1h (cp.async, 4-stage ring), out fp16.
// MODE 2: A=g_out2h (cp.async, 4-stage ring), out fp32; blockIdx.y = col half.
// ---------------------------------------------------------------------------
template <int MODE>
__global__ __launch_bounds__(256, 2)
void gemm_h(const float* __restrict__ Aupd, const float* __restrict__ bias0,
            const float* __restrict__ bias1, float* __restrict__ outp, int N) {
    extern __shared__ __align__(16) uint32_t smu[];

    const int tid = threadIdx.x;
    const int lane = tid & 31, warp = tid >> 5;
    const int wmB = (warp >> 2) * 64;  // 0 / 64
    const int wnB = (warp & 3) * 32;   // 0..96
    const int qr = lane >> 2, qc = lane & 3;
    const int row0 = blockIdx.x * 128;
    const int g = blockIdx.y;
    const uint32_t smb = smaddr(smu);

    int K, ldB, j1 = 0, j2 = 0, c1 = 0, c2 = 0;
    const __half* Bsrc;
    const float* bias;
    const __half* Ah = nullptr;
    int ldA = 0, ldO = 0, colO = 0;
    __half* Dh = nullptr;
    if (MODE == 0) {
        if (g == 0) { K = 1280; Bsrc = g_W10h; ldB = 1280; bias = bias0; }
        else {
            const int p1[6] = {5, 7, 8, 11, 13, 14};
            const int p2[6] = {6, 9, 10, 12, 15, 16};
            K = 512; Bsrc = g_W1h + (size_t)(g - 1) * 65536; ldB = 512;
            bias = bias1 + (g - 1) * 128;
            j1 = p1[g - 1]; j2 = p2[g - 1];
        }
        Dh = g_out1h; ldO = 896; colO = g * 128;
    } else if (MODE == 1) {
        const int q1[6] = {0, 1, 1, 1, 4, 4};
        const int q2[6] = {1, 2, 3, 4, 5, 6};
        K = 256; Bsrc = g_W2h + (size_t)g * 32768; ldB = 256;
        bias = bias0 + g * 128;
        c1 = q1[g] * 128; c2 = q2[g] * 128;
        Ah = g_out1h; ldA = 896; Dh = g_out2h; ldO = 768; colO = g * 128;
    } else {
        K = 768; Bsrc = g_Wfh + (size_t)g * 128 * 768; ldB = 768;
        bias = bias0 + g * 128;
        Ah = g_out2h; ldA = 768; colO = g * 128;
    }
    const int nk = K >> 5;

    float acc[4][4][4];
#pragma unroll
    for (int i = 0; i < 4; i++)
#pragma unroll
        for (int j = 0; j < 4; j++)
#pragma unroll
            for (int k = 0; k < 4; k++) acc[i][j][k] = 0.f;

    // ---- compute one 32-K chunk: 2 k16-steps x 16 MMAs ----
    auto compute = [&](int stage) {
        const uint32_t* Au = smu + stage * STG_U32;
        const uint32_t* Bu = Au + 128 * 20;
#pragma unroll
        for (int s = 0; s < 2; s++) {
            const int o = 8 * s;
            unsigned a[4][4], b[4][2];
#pragma unroll
            for (int mt = 0; mt < 4; mt++) {
                const uint32_t* p = Au + (wmB + mt * 16 + qr) * 20 + qc + o;
                a[mt][0] = p[0];
                a[mt][1] = p[160];  // +8 rows * 20
                a[mt][2] = p[4];
                a[mt][3] = p[164];
            }
#pragma unroll
            for (int nt = 0; nt < 4; nt++) {
                const uint32_t* p = Bu + (wnB + nt * 8 + qr) * 20 + qc + o;
                b[nt][0] = p[0];
                b[nt][1] = p[4];
            }
#pragma unroll
            for (int mt = 0; mt < 4; mt++)
#pragma unroll
                for (int nt = 0; nt < 4; nt++) mma16(acc[mt][nt], a[mt], b[nt]);
        }
    };

    if (MODE == 0) {
        // ---- A: LDG fp32 -> pack -> STS; B: cp.async; 2 stages ----
        uint32_t au[8];
        auto ldgA = [&](int ci) {
            const int k0 = ci * 32;
            const int joff =
                (g == 0) ? k0 : (((k0 < 256) ? j1 : j2) * 256 + (k0 & 255));
#pragma unroll
            for (int u = 0; u < 4; u++) {
                const int idx = tid + u * 256, row = idx >> 3, seg = idx & 7;
                int r = row0 + row;
                if (r > N - 1) r = N - 1;
                const float4 v =
                    *(const float4*)(Aupd + (size_t)r * 4352 + joff + seg * 4);
                au[2 * u] = packh(v.y, v.x);
                au[2 * u + 1] = packh(v.w, v.z);
            }
        };
        auto stsA = [&](int stage) {
            const uint32_t base = smb + (uint32_t)stage * STG_BYTES;
#pragma unroll
            for (int u = 0; u < 4; u++) {
                const int idx = tid + u * 256, row = idx >> 3, seg = idx & 7;
                sts64(base + (uint32_t)(row * 20 + seg * 2) * 4, au[2 * u],
                      au[2 * u + 1]);
            }
        };
        auto cpB = [&](int ci, int stage) {
            const int k0 = ci * 32;
            const uint32_t Bb = smb + (uint32_t)stage * STG_BYTES + 128 * 80;
#pragma unroll
            for (int u = 0; u < 2; u++) {  // 128 rows x 4 segs / 256 thr
                const int idx = tid + u * 256, row = idx >> 2, gs = idx & 3;
                cpa_cg(Bb + (uint32_t)(row * 20 + gs * 4) * 4,
                       Bsrc + (size_t)row * ldB + k0 + gs * 8);
            }
            cp_commit();
        };

        ldgA(0); stsA(0); cpB(0, 0);
        ldgA(1);
        for (int i = 0; i < nk; i++) {
            cp_wait(0);
            __syncthreads();
            if (i + 1 < nk) { stsA((i + 1) & 1); cpB(i + 1, (i + 1) & 1); }
            if (i + 2 < nk) ldgA(i + 2);
            compute(i & 1);
        }
    } else {
        // ---- A and B fp16 via cp.async; 4-stage ring ----
        auto issue = [&](int ci) {
            const int k0 = ci * 32, stage = ci & 3;
            const uint32_t Abp = smb + (uint32_t)stage * STG_BYTES;
            const uint32_t Bbp = Abp + 128 * 80;
            const int joff =
                (MODE == 1) ? ((k0 < 128) ? (c1 + k0) : (c2 + k0 - 128)) : k0;
#pragma unroll
            for (int u = 0; u < 2; u++) {
                const int idx = tid + u * 256, row = idx >> 2, gs = idx & 3;
                cpa_cg(Abp + (uint32_t)(row * 20 + gs * 4) * 4,
                       Ah + (size_t)(row0 + row) * ldA + joff + gs * 8);
            }
#pragma unroll
            for (int u = 0; u < 2; u++) {
                const int idx = tid + u * 256, row = idx >> 2, gs = idx & 3;
                cpa_cg(Bbp + (uint32_t)(row * 20 + gs * 4) * 4,
                       Bsrc + (size_t)row * ldB + k0 + gs * 8);
            }
            cp_commit();
        };

        issue(0); issue(1); issue(2);
        for (int i = 0; i < nk; i++) {
            const int rem = nk - 1 - i;
            cp_wait(rem < 2 ? rem : 2);
            __syncthreads();
            if (i + 3 < nk) issue(i + 3);
            compute(i & 3);
        }
    }

    // ---- epilogue: bias + relu ----
#pragma unroll
    for (int mt = 0; mt < 4; mt++) {
        const int r0 = row0 + wmB + mt * 16 + qr;
#pragma unroll
        for (int nt = 0; nt < 4; nt++) {
            const int lc = wnB + nt * 8 + 2 * qc;
            const float bb0 = __ldg(bias + lc);
            const float bb1 = __ldg(bias + lc + 1);
            const float v0 = fmaxf(acc[mt][nt][0] + bb0, 0.f);
            const float v1 = fmaxf(acc[mt][nt][1] + bb1, 0.f);
            const float v2 = fmaxf(acc[mt][nt][2] + bb0, 0.f);
            const float v3 = fmaxf(acc[mt][nt][3] + bb1, 0.f);
            if (MODE < 2) {
                if (r0 < N)
                    *(uint32_t*)&Dh[(size_t)r0 * ldO + colO + lc] = packh(v1, v0);
                if (r0 + 8 < N)
                    *(uint32_t*)&Dh[(size_t)(r0 + 8) * ldO + colO + lc] =
                        packh(v3, v2);
            } else {
                if (r0 < N)
                    *(float2*)&outp[(size_t)r0 * 256 + colO + lc] =
                        make_float2(v0, v1);
                if (r0 + 8 < N)
                    *(float2*)&outp[(size_t)(r0 + 8) * 256 + colO + lc] =
                        make_float2(v2, v3);
            }
        }
    }
}

// ---------------------------------------------------------------------------
extern "C" void kernel_launch(void* const* d_in, const int* in_sizes, int n_in,
                              void* d_out, int out_size) {
    const float* upd = (const float*)d_in[0];
    const float* W10 = (const float*)d_in[1];
    const float* b10 = (const float*)d_in[2];
    const float* W1  = (const float*)d_in[3];
    const float* b1  = (const float*)d_in[4];
    const float* W2  = (const float*)d_in[5];
    const float* b2  = (const float*)d_in[6];
    const float* Wf  = (const float*)d_in[7];
    const float* bf  = (const float*)d_in[8];
    const int N = in_sizes[0] / (17 * 256);

    const int smem0 = 2 * STG_BYTES;   // 40960
    const int smem12 = 4 * STG_BYTES;  // 81920
    cudaFuncSetAttribute(gemm_h<0>, cudaFuncAttributeMaxDynamicSharedMemorySize, smem0);
    cudaFuncSetAttribute(gemm_h<1>, cudaFuncAttributeMaxDynamicSharedMemorySize, smem12);
    cudaFuncSetAttribute(gemm_h<2>, cudaFuncAttributeMaxDynamicSharedMemorySize, smem12);

    cvt_weights<<<256, 256>>>(W10, W1, W2, Wf);

    const int t128 = (N + 127) / 128;
    gemm_h<0><<<dim3(t128, 7), 256, smem0>>>(upd, b10, b1, nullptr, N);
    gemm_h<1><<<dim3(t128, 6), 256, smem12>>>(nullptr, b2, nullptr, nullptr, N);
    gemm_h<2><<<dim3(t128, 2), 256, smem12>>>(nullptr, bf, nullptr, (float*)d_out, N);
}

// round 13
// speedup vs baseline: 1.4459x; 1.0945x over previous
#include <cuda_runtime.h>
#include <cuda_fp16.h>
#include <cstdint>

// ---------------------------------------------------------------------------
// HierarchUpdateMlp — fp16 mma.sync m16n8k16, fp32 accum.
// R12 = R6 (best, 444.5us) with stages B+C fused into one kernel:
//   k0    : stage A, 7 GEMMs (CTA 256x128, K=1280/512) -> g_out1h (fp16)
//   fused : per 128-row CTA x 6 groups: stage-B GEMM (K=256, pair gather)
//           -> relu -> SMEM S2 (fp16) -> stage-C GEMM accumulated in regs
//           -> final bias+relu -> out (fp32).
// Eliminates the g_out2 DRAM roundtrip + one launch. MMA math identical to R6.
// ---------------------------------------------------------------------------

#define NPAD 50176  // = ceil(50000/256)*256

__device__ __align__(16) __half g_out1h[(size_t)NPAD * 896];
__device__ __align__(16) __half g_W10h[128 * 1280];
__device__ __align__(16) __half g_W1h[6 * 128 * 512];
__device__ __align__(16) __half g_W2h[6 * 128 * 256];
__device__ __align__(16) __half g_Wfh[256 * 768];

#define STG0_U32 7680              // k0: (256+128)*20 u32 per stage
#define STG0_BYTES (STG0_U32 * 4)  // 30720
#define F_STG_U32 5120             // fused ring: 256*20 u32 per stage
#define F_STG_BYTES (F_STG_U32 * 4)

__device__ __forceinline__ uint32_t smaddr(const void* p) {
    uint32_t a;
    asm("{ .reg .u64 t; cvta.to.shared.u64 t, %1; cvt.u32.u64 %0, t; }"
        : "=r"(a) : "l"(p));
    return a;
}
__device__ __forceinline__ uint32_t packh(float hi, float lo) {
    uint32_t r;
    asm("cvt.rn.f16x2.f32 %0, %1, %2;" : "=r"(r) : "f"(hi), "f"(lo));
    return r;
}
__device__ __forceinline__ void cpa_cg(uint32_t d, const void* s) {
    asm volatile("cp.async.cg.shared.global [%0], [%1], 16;" :: "r"(d), "l"(s)
                 : "memory");
}
__device__ __forceinline__ void cp_commit() {
    asm volatile("cp.async.commit_group;" ::: "memory");
}
__device__ __forceinline__ void cp_wait(int allowed) {
    if (allowed >= 2) asm volatile("cp.async.wait_group 2;" ::: "memory");
    else if (allowed == 1) asm volatile("cp.async.wait_group 1;" ::: "memory");
    else asm volatile("cp.async.wait_group 0;" ::: "memory");
}
__device__ __forceinline__ void sts64(uint32_t a, uint32_t x, uint32_t y) {
    asm volatile("st.shared.v2.b32 [%0], {%1,%2};" :: "r"(a), "r"(x), "r"(y)
                 : "memory");
}
__device__ __forceinline__ void mma16(float (&c)[4], const unsigned (&a)[4],
                                      const unsigned (&b)[2]) {
    asm volatile(
        "mma.sync.aligned.m16n8k16.row.col.f32.f16.f16.f32 "
        "{%0,%1,%2,%3},{%4,%5,%6,%7},{%8,%9},{%0,%1,%2,%3};\n"
        : "+f"(c[0]), "+f"(c[1]), "+f"(c[2]), "+f"(c[3])
        : "r"(a[0]), "r"(a[1]), "r"(a[2]), "r"(a[3]), "r"(b[0]), "r"(b[1]));
}

// ---------------------------------------------------------------------------
__global__ void cvt_weights(const float* __restrict__ W10,
                            const float* __restrict__ W1,
                            const float* __restrict__ W2,
                            const float* __restrict__ Wf) {
    int i = blockIdx.x * blockDim.x + threadIdx.x;
    int st = gridDim.x * blockDim.x;
    for (int j = i; j < 128 * 1280; j += st) g_W10h[j] = __float2half_rn(W10[j]);
    for (int j = i; j < 6 * 128 * 512; j += st) g_W1h[j] = __float2half_rn(W1[j]);
    for (int j = i; j < 6 * 128 * 256; j += st) g_W2h[j] = __float2half_rn(W2[j]);
    for (int j = i; j < 256 * 768; j += st) g_Wfh[j] = __float2half_rn(Wf[j]);
}

// ---------------------------------------------------------------------------
// Stage A (exact R6 MODE-0): CTA 256x128, 8 warps (4m x 2n), warp 64x64,
// A: LDG fp32 -> pack -> STS (2 stages); B: cp.async. K-chunk 32.
// ---------------------------------------------------------------------------
__global__ __launch_bounds__(256, 1)
void stageA(const float* __restrict__ Aupd, const float* __restrict__ b10,
            const float* __restrict__ b1, int N) {
    extern __shared__ __align__(16) uint32_t smu[];

    const int tid = threadIdx.x;
    const int lane = tid & 31, warp = tid >> 5;
    const int wm = warp >> 1, wn = warp & 1;
    const int qr = lane >> 2, qc = lane & 3;
    const int row0 = blockIdx.x * 256;
    const int g = blockIdx.y;
    const uint32_t smb = smaddr(smu);

    int K, ldB, j1 = 0, j2 = 0;
    const __half* Bsrc;
    const float* bias;
    if (g == 0) { K = 1280; Bsrc = g_W10h; ldB = 1280; bias = b10; }
    else {
        const int p1[6] = {5, 7, 8, 11, 13, 14};
        const int p2[6] = {6, 9, 10, 12, 15, 16};
        K = 512; Bsrc = g_W1h + (size_t)(g - 1) * 65536; ldB = 512;
        bias = b1 + (g - 1) * 128;
        j1 = p1[g - 1]; j2 = p2[g - 1];
    }
    const int nk = K >> 5;

    float acc[4][8][4];
#pragma unroll
    for (int i = 0; i < 4; i++)
#pragma unroll
        for (int j = 0; j < 8; j++)
#pragma unroll
            for (int k = 0; k < 4; k++) acc[i][j][k] = 0.f;

    auto compute = [&](int stage) {
        const uint32_t* Au = smu + stage * STG0_U32;
        const uint32_t* Bu = Au + 256 * 20;
#pragma unroll
        for (int s = 0; s < 2; s++) {
            const int o = 8 * s;
            unsigned a[4][4], b[8][2];
#pragma unroll
            for (int mt = 0; mt < 4; mt++) {
                const uint32_t* p = Au + (wm * 64 + mt * 16 + qr) * 20 + qc + o;
                a[mt][0] = p[0];
                a[mt][1] = p[160];
                a[mt][2] = p[4];
                a[mt][3] = p[164];
            }
#pragma unroll
            for (int nt = 0; nt < 8; nt++) {
                const uint32_t* p = Bu + (wn * 64 + nt * 8 + qr) * 20 + qc + o;
                b[nt][0] = p[0];
                b[nt][1] = p[4];
            }
#pragma unroll
            for (int mt = 0; mt < 4; mt++)
#pragma unroll
                for (int nt = 0; nt < 8; nt++) mma16(acc[mt][nt], a[mt], b[nt]);
        }
    };

    float4 ar[8];
    auto ldgA = [&](int ci) {
        const int k0 = ci * 32;
        const int joff =
            (g == 0) ? k0 : (((k0 < 256) ? j1 : j2) * 256 + (k0 & 255));
#pragma unroll
        for (int u = 0; u < 8; u++) {
            const int idx = tid + u * 256, row = idx >> 3, seg = idx & 7;
            int r = row0 + row;
            if (r > N - 1) r = N - 1;
            ar[u] = *(const float4*)(Aupd + (size_t)r * 4352 + joff + seg * 4);
        }
    };
    auto stsA = [&](int stage) {
        const uint32_t base = smb + (uint32_t)stage * STG0_BYTES;
#pragma unroll
        for (int u = 0; u < 8; u++) {
            const int idx = tid + u * 256, row = idx >> 3, seg = idx & 7;
            sts64(base + (uint32_t)(row * 20 + seg * 2) * 4,
                  packh(ar[u].y, ar[u].x), packh(ar[u].w, ar[u].z));
        }
    };
    auto cpB = [&](int ci, int stage) {
        const int k0 = ci * 32;
        const uint32_t Bb = smb + (uint32_t)stage * STG0_BYTES + 256 * 80;
#pragma unroll
        for (int u = 0; u < 2; u++) {
            const int idx = tid + u * 256, row = idx >> 2, gs = idx & 3;
            cpa_cg(Bb + (uint32_t)(row * 20 + gs * 4) * 4,
                   Bsrc + (size_t)row * ldB + k0 + gs * 8);
        }
        cp_commit();
    };

    ldgA(0); stsA(0); cpB(0, 0);
    ldgA(1);
    for (int i = 0; i < nk; i++) {
        cp_wait(0);
        __syncthreads();
        if (i + 1 < nk) { stsA((i + 1) & 1); cpB(i + 1, (i + 1) & 1); }
        if (i + 2 < nk) ldgA(i + 2);
        compute(i & 1);
    }

#pragma unroll
    for (int mt = 0; mt < 4; mt++) {
        const int r0 = row0 + wm * 64 + mt * 16 + qr;
#pragma unroll
        for (int nt = 0; nt < 8; nt++) {
            const int lc = wn * 64 + nt * 8 + 2 * qc;
            const float bb0 = __ldg(bias + lc);
            const float bb1 = __ldg(bias + lc + 1);
            const float v0 = fmaxf(acc[mt][nt][0] + bb0, 0.f);
            const float v1 = fmaxf(acc[mt][nt][1] + bb1, 0.f);
            const float v2 = fmaxf(acc[mt][nt][2] + bb0, 0.f);
            const float v3 = fmaxf(acc[mt][nt][3] + bb1, 0.f);
            if (r0 < N)
                *(uint32_t*)&g_out1h[(size_t)r0 * 896 + g * 128 + lc] =
                    packh(v1, v0);
            if (r0 + 8 < N)
                *(uint32_t*)&g_out1h[(size_t)(r0 + 8) * 896 + g * 128 + lc] =
                    packh(v3, v2);
        }
    }
}

// ---------------------------------------------------------------------------
// Fused stages B+C. CTA 128 rows, 256 threads, 8 warps (2m x 4n).
// Ring: 4 stages x 5120 u32. S2: 128 x 68 u32 (fp16 pairs, conflict-free).
// Phase B per group: M=128,N=128,K=256; warp tile 64x32; acc2 64 regs.
// Phase C per group: M=128,N=256,K=128; warp tile 64x64; fAcc 128 regs,
// accumulated over all 6 groups, final bias+relu -> fp32 out.
// ---------------------------------------------------------------------------
__global__ __launch_bounds__(256, 1)
void fusedBC(const float* __restrict__ b2, const float* __restrict__ bf,
             float* __restrict__ outp, int N) {
    extern __shared__ __align__(16) uint32_t smu[];
    uint32_t* S2 = smu + 4 * F_STG_U32;

    const int tid = threadIdx.x;
    const int lane = tid & 31, warp = tid >> 5;
    const int wmB = (warp >> 2) * 64;  // 0 / 64
    const int wn4 = warp & 3;          // 0..3
    const int qr = lane >> 2, qc = lane & 3;
    const int row0 = blockIdx.x * 128;
    const uint32_t smb = smaddr(smu);

    const int q1[6] = {0, 1, 1, 1, 4, 4};
    const int q2[6] = {1, 2, 3, 4, 5, 6};

    float fAcc[4][8][4];
#pragma unroll
    for (int i = 0; i < 4; i++)
#pragma unroll
        for (int j = 0; j < 8; j++)
#pragma unroll
            for (int k = 0; k < 4; k++) fAcc[i][j][k] = 0.f;

    for (int g = 0; g < 6; g++) {
        const __half* W2g = g_W2h + (size_t)g * 32768;
        const int c1 = q1[g] * 128, c2 = q2[g] * 128;

        // ================= phase B: acc2 = relu-input GEMM =================
        float acc2[4][4][4];
#pragma unroll
        for (int i = 0; i < 4; i++)
#pragma unroll
            for (int j = 0; j < 4; j++)
#pragma unroll
                for (int k = 0; k < 4; k++) acc2[i][j][k] = 0.f;

        auto issueB = [&](int ci) {
            const int k0 = ci * 32, st = ci & 3;
            const uint32_t Ab = smb + (uint32_t)st * F_STG_BYTES;
            const uint32_t Bb = Ab + 128 * 80;
            const int joff = (k0 < 128) ? (c1 + k0) : (c2 + k0 - 128);
#pragma unroll
            for (int u = 0; u < 2; u++) {
                const int idx = tid + u * 256, row = idx >> 2, gs = idx & 3;
                cpa_cg(Ab + (uint32_t)(row * 20 + gs * 4) * 4,
                       g_out1h + (size_t)(row0 + row) * 896 + joff + gs * 8);
            }
#pragma unroll
            for (int u = 0; u < 2; u++) {
                const int idx = tid + u * 256, row = idx >> 2, gs = idx & 3;
                cpa_cg(Bb + (uint32_t)(row * 20 + gs * 4) * 4,
                       W2g + (size_t)row * 256 + k0 + gs * 8);
            }
            cp_commit();
        };

        issueB(0); issueB(1); issueB(2);
        for (int i = 0; i < 8; i++) {
            const int rem = 7 - i;
            cp_wait(rem < 2 ? rem : 2);
            __syncthreads();
            if (i + 3 < 8) issueB(i + 3);
            const uint32_t* Au = smu + (i & 3) * F_STG_U32;
            const uint32_t* Bu = Au + 128 * 20;
#pragma unroll
            for (int s = 0; s < 2; s++) {
                const int o = 8 * s;
                unsigned a[4][4], b[4][2];
#pragma unroll
                for (int mt = 0; mt < 4; mt++) {
                    const uint32_t* p =
                        Au + (wmB + mt * 16 + qr) * 20 + qc + o;
                    a[mt][0] = p[0];
                    a[mt][1] = p[160];
                    a[mt][2] = p[4];
                    a[mt][3] = p[164];
                }
#pragma unroll
                for (int nt = 0; nt < 4; nt++) {
                    const uint32_t* p =
                        Bu + (wn4 * 32 + nt * 8 + qr) * 20 + qc + o;
                    b[nt][0] = p[0];
                    b[nt][1] = p[4];
                }
#pragma unroll
                for (int mt = 0; mt < 4; mt++)
#pragma unroll
                    for (int nt = 0; nt < 4; nt++)
                        mma16(acc2[mt][nt], a[mt], b[nt]);
            }
        }

        // epilogue B: bias + relu + pack -> S2 (stride 68 u32)
#pragma unroll
        for (int mt = 0; mt < 4; mt++) {
            const int row = wmB + mt * 16 + qr;
#pragma unroll
            for (int nt = 0; nt < 4; nt++) {
                const int lc = wn4 * 32 + nt * 8 + 2 * qc;
                const float bb0 = __ldg(b2 + g * 128 + lc);
                const float bb1 = __ldg(b2 + g * 128 + lc + 1);
                const int cu = wn4 * 16 + nt * 4 + qc;
                S2[row * 68 + cu] =
                    packh(fmaxf(acc2[mt][nt][1] + bb1, 0.f),
                          fmaxf(acc2[mt][nt][0] + bb0, 0.f));
                S2[(row + 8) * 68 + cu] =
                    packh(fmaxf(acc2[mt][nt][3] + bb1, 0.f),
                          fmaxf(acc2[mt][nt][2] + bb0, 0.f));
            }
        }
        __syncthreads();  // S2 complete; ring free

        // ============ phase C: fAcc += S2 @ Wf_g^T (N=256, K=128) ===========
        auto issueC = [&](int ci) {
            const int k0 = ci * 32, st = ci & 3;
            const uint32_t Bb = smb + (uint32_t)st * F_STG_BYTES;
#pragma unroll
            for (int u = 0; u < 4; u++) {
                const int idx = tid + u * 256, row = idx >> 2, gs = idx & 3;
                cpa_cg(Bb + (uint32_t)(row * 20 + gs * 4) * 4,
                       g_Wfh + (size_t)row * 768 + g * 128 + k0 + gs * 8);
            }
            cp_commit();
        };

        issueC(0); issueC(1); issueC(2);
        for (int i = 0; i < 4; i++) {
            const int rem = 3 - i;
            cp_wait(rem < 2 ? rem : 2);
            __syncthreads();
            if (i + 3 < 4) issueC(3);
            const uint32_t* Bu = smu + (i & 3) * F_STG_U32;
#pragma unroll
            for (int s = 0; s < 2; s++) {
                const int o = 8 * s;
                unsigned a[4][4], b[8][2];
#pragma unroll
                for (int mt = 0; mt < 4; mt++) {
                    const uint32_t* p =
                        S2 + (wmB + mt * 16 + qr) * 68 + i * 16 + o + qc;
                    a[mt][0] = p[0];
                    a[mt][1] = p[544];  // +8 rows * 68
                    a[mt][2] = p[4];
                    a[mt][3] = p[548];
                }
#pragma unroll
                for (int nt = 0; nt < 8; nt++) {
                    const uint32_t* p =
                        Bu + (wn4 * 64 + nt * 8 + qr) * 20 + qc + o;
                    b[nt][0] = p[0];
                    b[nt][1] = p[4];
                }
#pragma unroll
                for (int mt = 0; mt < 4; mt++)
#pragma unroll
                    for (int nt = 0; nt < 8; nt++)
                        mma16(fAcc[mt][nt], a[mt], b[nt]);
            }
        }
        __syncthreads();  // ring + S2 safe to reuse for next group
    }

    // ---- final epilogue: bias + relu -> fp32 out ----
#pragma unroll
    for (int mt = 0; mt < 4; mt++) {
        const int r0 = row0 + wmB + mt * 16 + qr;
#pragma unroll
        for (int nt = 0; nt < 8; nt++) {
            const int lc = wn4 * 64 + nt * 8 + 2 * qc;
            const float bb0 = __ldg(bf + lc);
            const float bb1 = __ldg(bf + lc + 1);
            if (r0 < N)
                *(float2*)&outp[(size_t)r0 * 256 + lc] =
                    make_float2(fmaxf(fAcc[mt][nt][0] + bb0, 0.f),
                                fmaxf(fAcc[mt][nt][1] + bb1, 0.f));
            if (r0 + 8 < N)
                *(float2*)&outp[(size_t)(r0 + 8) * 256 + lc] =
                    make_float2(fmaxf(fAcc[mt][nt][2] + bb0, 0.f),
                                fmaxf(fAcc[mt][nt][3] + bb1, 0.f));
        }
    }
}

// ---------------------------------------------------------------------------
extern "C" void kernel_launch(void* const* d_in, const int* in_sizes, int n_in,
                              void* d_out, int out_size) {
    const float* upd = (const float*)d_in[0];
    const float* W10 = (const float*)d_in[1];
    const float* b10 = (const float*)d_in[2];
    const float* W1  = (const float*)d_in[3];
    const float* b1  = (const float*)d_in[4];
    const float* W2  = (const float*)d_in[5];
    const float* b2  = (const float*)d_in[6];
    const float* Wf  = (const float*)d_in[7];
    const float* bf  = (const float*)d_in[8];
    const int N = in_sizes[0] / (17 * 256);

    const int smemA = 2 * STG0_BYTES;                 // 61440
    const int smemF = 4 * F_STG_BYTES + 128 * 68 * 4; // 81920 + 34816 = 116736
    cudaFuncSetAttribute(stageA, cudaFuncAttributeMaxDynamicSharedMemorySize, smemA);
    cudaFuncSetAttribute(fusedBC, cudaFuncAttributeMaxDynamicSharedMemorySize, smemF);

    cvt_weights<<<256, 256>>>(W10, W1, W2, Wf);

    const int t256 = (N + 255) / 256;
    const int t128 = (N + 127) / 128;
    stageA<<<dim3(t256, 7), 256, smemA>>>(upd, b10, b1, N);
    fusedBC<<<t128, 256, smemF>>>(b2, bf, (float*)d_out, N);
}